// round 7
// baseline (speedup 1.0000x reference)
#include <cuda_runtime.h>
#include <math.h>
#include <stdint.h>

#define NPIX 4096
#define PADW 66
#define PADN 4356
#define BATCH 2
#define CVCH 256
#define CQKCH 320
#define DPCH 64
#define NHID 128

// ---------------- scratch arena ----------------
constexpr size_t SZ_QK = (size_t)BATCH * CQKCH * NPIX;
constexpr size_t SZ_CV = (size_t)BATCH * CVCH * NPIX;
constexpr size_t SZ_DP = (size_t)BATCH * DPCH * NPIX;

constexpr size_t OFF_QUERY = 0;
constexpr size_t OFF_KEYT  = OFF_QUERY + SZ_QK;
constexpr size_t OFF_QF    = OFF_KEYT + SZ_QK;
constexpr size_t OFF_KF    = OFF_QF + SZ_QK;
constexpr size_t OFF_QP    = OFF_KF + SZ_QK;
constexpr size_t OFF_KP    = OFF_QP + SZ_DP;
constexpr size_t OFF_VH    = OFF_KP + SZ_DP;
constexpr size_t OFF_OUT   = OFF_VH + SZ_CV;
constexpr size_t OFF_STATS = OFF_OUT + SZ_CV;
constexpr size_t OFF_CONF  = OFF_STATS + (size_t)BATCH*NPIX*4;
constexpr size_t OFF_ACTV  = OFF_CONF + (size_t)BATCH*NPIX;
constexpr size_t OFF_GAMMA = OFF_ACTV + (size_t)BATCH*NHID*PADN;
constexpr size_t OFF_BETA  = OFF_GAMMA + SZ_CV;
constexpr size_t OFF_INST  = OFF_BETA + SZ_CV;
constexpr size_t OFF_YPRE  = OFF_INST + (size_t)BATCH*CVCH*2;
constexpr size_t OFF_PST   = OFF_YPRE + SZ_CV;
constexpr size_t OFF_YPAD  = OFF_PST + (size_t)BATCH*NPIX*2;
constexpr size_t OFF_T1PAD = OFF_YPAD + (size_t)BATCH*CVCH*PADN;
constexpr size_t OFF_SEGP  = OFF_T1PAD + (size_t)BATCH*CVCH*PADN;
constexpr size_t OFF_WT    = OFF_SEGP + 26176;
constexpr size_t WT_F   = 0;
constexpr size_t WT_G   = WT_F  + 320*320;
constexpr size_t WT_H   = WT_G  + 320*320;
constexpr size_t WT_FP  = WT_H  + 256*256;
constexpr size_t WT_GP  = WT_FP + 320*64;
constexpr size_t WT_SPS = WT_GP + 320*64;
constexpr size_t WT_SPG = WT_SPS + 9*3*128;
constexpr size_t WT_SPB = WT_SPG + 9*128*256;
constexpr size_t WT_R1  = WT_SPB + 9*128*256;
constexpr size_t WT_R2  = WT_R1  + 9*256*256;
constexpr size_t WT_END = WT_R2  + 9*256*256;
constexpr size_t OFF_MASK = OFF_WT + ((WT_END + 63) & ~(size_t)63);
constexpr size_t ARENA_FLOATS = OFF_MASK + ((size_t)BATCH*NPIX*NPIX)/4 + 64;

__device__ __align__(16) float g_arena[ARENA_FLOATS];

// ---------------- packed f32x2 FMA + fast exp ----------------
__device__ __forceinline__ unsigned long long ffma2(unsigned long long a,
                                                    unsigned long long b,
                                                    unsigned long long c){
    unsigned long long d;
    asm("fma.rn.f32x2 %0, %1, %2, %3;" : "=l"(d) : "l"(a), "l"(b), "l"(c));
    return d;
}
__device__ __forceinline__ float2 asf2(unsigned long long u){
    union { unsigned long long u; float2 f; } x; x.u = u; return x.f;
}

// exp(x) for x <= 0, FMA/ALU pipes only (no MUFU). rel err ~1e-6.
__device__ __forceinline__ float fast_exp(float x){
    float t = x * 1.4426950408889634f;
    t = fmaxf(t, -126.0f);
    float tr = t + 12582912.0f;              // RN to integer in low mantissa
    int   k  = __float_as_int(tr) - 0x4B400000;
    float fi = tr - 12582912.0f;
    float f  = t - fi;                       // [-0.5, 0.5]
    float p = 1.0f + f*(0.6931471805599453f + f*(0.2402265069591007f
              + f*(0.0555041086648216f + f*0.0096181291076285f)));
    return p * __int_as_float((k + 127) << 23);
}

// ---------------- utility kernels ----------------
__global__ void zero_kernel(float* p, int n){
    int i = blockIdx.x * blockDim.x + threadIdx.x;
    if (i < n) p[i] = 0.f;
}

__global__ void transpose_w(const float* __restrict__ src, float* __restrict__ dst,
                            int M, int K, int taps){
    int idx = blockIdx.x * blockDim.x + threadIdx.x;
    if (idx >= M * K * taps) return;
    int t = idx / (K * M);
    int r = idx % (K * M);
    int k = r / M;
    int m = r % M;
    dst[idx] = src[((size_t)m * K + k) * taps + t];
}

__global__ void pad_seg(const float* __restrict__ seg, float* __restrict__ dst){
    int idx = blockIdx.x * blockDim.x + threadIdx.x;
    if (idx >= BATCH * 3 * PADN) return;
    int bc = idx / PADN;
    int r = idx % PADN;
    int yy = r / PADW, xx = r % PADW;
    float v = 0.f;
    if (yy >= 1 && yy <= 64 && xx >= 1 && xx <= 64)
        v = seg[(size_t)bc * NPIX + (yy - 1) * 64 + (xx - 1)];
    dst[idx] = v;
}

__global__ __launch_bounds__(256) void norm_concat(
    const float* __restrict__ q, const float* __restrict__ k,
    const float* __restrict__ pos, float* __restrict__ outq, float* __restrict__ outk){
    const float* src = blockIdx.y ? k : q;
    float* dst = blockIdx.y ? outk : outq;
    int b = blockIdx.x / 64, y = blockIdx.x % 64;
    int tid = threadIdx.x;
    int x = tid & 63, cl = tid >> 6;
    const float* sb = src + (size_t)b * CVCH * NPIX + y * 64;
    __shared__ float partial[4][64];
    __shared__ float inv[64];
    float ss = 0.f;
    for (int c = cl; c < CVCH; c += 4){ float v = sb[(size_t)c * NPIX + x]; ss += v * v; }
    partial[cl][x] = ss;
    __syncthreads();
    if (cl == 0){
        float s = partial[0][x] + partial[1][x] + partial[2][x] + partial[3][x];
        inv[x] = 1.f / (sqrtf(s) + 2.220446049250313e-16f);
    }
    __syncthreads();
    float* db = dst + (size_t)b * CQKCH * NPIX + y * 64;
    float iv = inv[x];
    for (int c = cl; c < CVCH; c += 4) db[(size_t)c * NPIX + x] = sb[(size_t)c * NPIX + x] * iv;
    const float* pb = pos + y * 64;
    for (int i = tid; i < 64 * 64; i += 256){
        int cp = i >> 6, xx = i & 63;
        db[(size_t)(CVCH + cp) * NPIX + xx] = pb[(size_t)cp * NPIX + xx];
    }
}

// ------------- W@X GEMM with f32x2 (tile M=64 x N=128, microtile 4x8) -------------
__global__ __launch_bounds__(256) void gemm_wx(
    const float* __restrict__ Wt, const float* __restrict__ X,
    const float* __restrict__ bias, float* __restrict__ Cout,
    int M, int K, int taps,
    long xBatchStride, int xChanStride, long cBatchStride,
    int relu, int outPadded,
    const float* __restrict__ addsrc, long addBatchStride)
{
    int b = blockIdx.z;
    int n0 = blockIdx.x * 128;
    int m0 = blockIdx.y * 64;
    const float* Xb = X + (size_t)b * xBatchStride;
    __shared__ __align__(16) float2 As2[16][64];
    __shared__ __align__(16) float  Bs[16][128];
    unsigned long long acc[4][4] = {};
    int tid = threadIdx.x;
    int tx = tid & 15, ty = tid >> 4;
    for (int tap = 0; tap < taps; ++tap){
        const float* Wtap = Wt + (size_t)tap * K * M + m0;
        int ky = tap / 3, kx = tap % 3;
        for (int k0 = 0; k0 < K; k0 += 16){
#pragma unroll
            for (int i = 0; i < 4; ++i){
                int idx = tid + 256 * i;
                int kk = idx >> 6, r = idx & 63;
                int kg = k0 + kk;
                float av = (kg < K) ? Wtap[(size_t)kg * M + r] : 0.f;
                As2[kk][r] = make_float2(av, av);
            }
#pragma unroll
            for (int i = 0; i < 8; ++i){
                int idx = tid + 256 * i;
                int kk = idx >> 7, col = idx & 127;
                int kg = k0 + kk;
                float bv = 0.f;
                if (kg < K){
                    if (taps == 1) bv = Xb[(size_t)kg * xChanStride + n0 + col];
                    else {
                        int n = n0 + col, yy = n >> 6, xx = n & 63;
                        bv = Xb[(size_t)kg * xChanStride + (yy + ky) * PADW + xx + kx];
                    }
                }
                Bs[kk][col] = bv;
            }
            __syncthreads();
#pragma unroll
            for (int kk = 0; kk < 16; ++kk){
                ulonglong2 a01 = *(const ulonglong2*)&As2[kk][ty * 4];
                ulonglong2 a23 = *(const ulonglong2*)&As2[kk][ty * 4 + 2];
                ulonglong2 b01 = *(const ulonglong2*)&Bs[kk][tx * 8];
                ulonglong2 b23 = *(const ulonglong2*)&Bs[kk][tx * 8 + 4];
                unsigned long long av[4] = {a01.x, a01.y, a23.x, a23.y};
                unsigned long long bv[4] = {b01.x, b01.y, b23.x, b23.y};
#pragma unroll
                for (int i = 0; i < 4; ++i)
#pragma unroll
                    for (int j = 0; j < 4; ++j)
                        acc[i][j] = ffma2(av[i], bv[j], acc[i][j]);
            }
            __syncthreads();
        }
    }
#pragma unroll
    for (int i = 0; i < 4; ++i){
        int m = m0 + ty * 4 + i;
        float bvv = bias ? bias[m] : 0.f;
        float vals[8];
#pragma unroll
        for (int j = 0; j < 4; ++j){
            float2 p = asf2(acc[i][j]);
            vals[j*2] = p.x + bvv; vals[j*2+1] = p.y + bvv;
        }
#pragma unroll
        for (int j = 0; j < 8; ++j){
            float v = vals[j];
            if (relu) v = fmaxf(v, 0.f);
            if (addsrc){
                int n = n0 + tx * 8 + j, yy = n >> 6, xx = n & 63;
                v += addsrc[(size_t)b * addBatchStride + (size_t)m * PADN + (size_t)(yy + 1) * PADW + xx + 1];
            }
            vals[j] = v;
        }
        if (outPadded){
#pragma unroll
            for (int j = 0; j < 8; ++j){
                int n = n0 + tx * 8 + j, yy = n >> 6, xx = n & 63;
                Cout[(size_t)b * cBatchStride + (size_t)m * PADN + (size_t)(yy + 1) * PADW + xx + 1] = vals[j];
            }
        } else {
            float* dst = &Cout[(size_t)b * cBatchStride + (size_t)m * NPIX + n0 + tx * 8];
            *(float4*)dst       = make_float4(vals[0], vals[1], vals[2], vals[3]);
            *(float4*)(dst + 4) = make_float4(vals[4], vals[5], vals[6], vals[7]);
        }
    }
}

// ---------------- cor + mask fused GEMM (tile n=64 x m=128) ----------------
__global__ __launch_bounds__(256) void gemm_corr(
    const float* __restrict__ qf, const float* __restrict__ kf,
    const float* __restrict__ qp, const float* __restrict__ kp,
    float* __restrict__ cor, unsigned char* __restrict__ mask)
{
    int b = blockIdx.z;
    int n0 = blockIdx.y * 64, m0 = blockIdx.x * 128;
    __shared__ __align__(16) float2 As2[16][64];
    __shared__ __align__(16) float  Bs[16][128];
    int tid = threadIdx.x, tx = tid & 15, ty = tid >> 4;
    unsigned long long acc[4][4] = {};
    const float* A  = qf + (size_t)b * CQKCH * NPIX + n0;
    const float* Bm = kf + (size_t)b * CQKCH * NPIX + m0;
    for (int k0 = 0; k0 < CQKCH; k0 += 16){
#pragma unroll
        for (int i = 0; i < 4; ++i){
            int idx = tid + 256 * i;
            int kk = idx >> 6, r = idx & 63;
            float av = A[(size_t)(k0 + kk) * NPIX + r];
            As2[kk][r] = make_float2(av, av);
        }
#pragma unroll
        for (int i = 0; i < 8; ++i){
            int idx = tid + 256 * i;
            int kk = idx >> 7, col = idx & 127;
            Bs[kk][col] = Bm[(size_t)(k0 + kk) * NPIX + col];
        }
        __syncthreads();
#pragma unroll
        for (int kk = 0; kk < 16; ++kk){
            ulonglong2 a01 = *(const ulonglong2*)&As2[kk][ty * 4];
            ulonglong2 a23 = *(const ulonglong2*)&As2[kk][ty * 4 + 2];
            ulonglong2 b01 = *(const ulonglong2*)&Bs[kk][tx * 8];
            ulonglong2 b23 = *(const ulonglong2*)&Bs[kk][tx * 8 + 4];
            unsigned long long av[4] = {a01.x, a01.y, a23.x, a23.y};
            unsigned long long bv[4] = {b01.x, b01.y, b23.x, b23.y};
#pragma unroll
            for (int i = 0; i < 4; ++i)
#pragma unroll
                for (int j = 0; j < 4; ++j)
                    acc[i][j] = ffma2(av[i], bv[j], acc[i][j]);
        }
        __syncthreads();
    }
    const float scale = rsqrtf((float)CQKCH);
    size_t corBase = (size_t)b * NPIX * NPIX;
#pragma unroll
    for (int i = 0; i < 4; ++i){
        int n = n0 + ty * 4 + i;
        float2 p0 = asf2(acc[i][0]), p1 = asf2(acc[i][1]), p2 = asf2(acc[i][2]), p3 = asf2(acc[i][3]);
        float* dst = &cor[corBase + (size_t)n * NPIX + m0 + tx * 8];
        *(float4*)dst       = make_float4(p0.x * scale, p0.y * scale, p1.x * scale, p1.y * scale);
        *(float4*)(dst + 4) = make_float4(p2.x * scale, p2.y * scale, p3.x * scale, p3.y * scale);
    }
    // mask pass (K = 64)
    unsigned long long acc2[4][4] = {};
    const float* Ap = qp + (size_t)b * DPCH * NPIX + n0;
    const float* Bp = kp + (size_t)b * DPCH * NPIX + m0;
    for (int k0 = 0; k0 < DPCH; k0 += 16){
#pragma unroll
        for (int i = 0; i < 4; ++i){
            int idx = tid + 256 * i;
            int kk = idx >> 6, r = idx & 63;
            float av = Ap[(size_t)(k0 + kk) * NPIX + r];
            As2[kk][r] = make_float2(av, av);
        }
#pragma unroll
        for (int i = 0; i < 8; ++i){
            int idx = tid + 256 * i;
            int kk = idx >> 7, col = idx & 127;
            Bs[kk][col] = Bp[(size_t)(k0 + kk) * NPIX + col];
        }
        __syncthreads();
#pragma unroll
        for (int kk = 0; kk < 16; ++kk){
            ulonglong2 a01 = *(const ulonglong2*)&As2[kk][ty * 4];
            ulonglong2 a23 = *(const ulonglong2*)&As2[kk][ty * 4 + 2];
            ulonglong2 b01 = *(const ulonglong2*)&Bs[kk][tx * 8];
            ulonglong2 b23 = *(const ulonglong2*)&Bs[kk][tx * 8 + 4];
            unsigned long long av[4] = {a01.x, a01.y, a23.x, a23.y};
            unsigned long long bv[4] = {b01.x, b01.y, b23.x, b23.y};
#pragma unroll
            for (int i = 0; i < 4; ++i)
#pragma unroll
                for (int j = 0; j < 4; ++j)
                    acc2[i][j] = ffma2(av[i], bv[j], acc2[i][j]);
        }
        __syncthreads();
    }
#pragma unroll
    for (int i = 0; i < 4; ++i){
        int n = n0 + ty * 4 + i;
        unsigned long long mv = 0;
#pragma unroll
        for (int j = 0; j < 4; ++j){
            float2 p = asf2(acc2[i][j]);
            mv |= (unsigned long long)(p.x > 0.f) << (16 * j);
            mv |= (unsigned long long)(p.y > 0.f) << (16 * j + 8);
        }
        *(unsigned long long*)&mask[corBase + (size_t)n * NPIX + m0 + tx * 8] = mv;
    }
}

// -------- per-row softmax stats (both variants) + conf --------
__global__ __launch_bounds__(256) void row_stats(
    const float* __restrict__ cor, const unsigned char* __restrict__ mask,
    float* __restrict__ stats, float* __restrict__ conf)
{
    int b = blockIdx.y, n = blockIdx.x;
    const float* row = cor + ((size_t)b * NPIX + n) * NPIX;
    const unsigned char* mrow = mask + ((size_t)b * NPIX + n) * NPIX;
    int t = threadIdx.x;
    float m1 = -1e30f, m2 = -1e30f;
    for (int i = t; i < NPIX; i += 256){
        float s = row[i];
        m1 = fmaxf(m1, s);
        m2 = fmaxf(m2, mrow[i] ? -10000.f : s);
    }
    __shared__ float r1[256], r2[256], r3[256];
    r1[t] = m1; r2[t] = m2;
    __syncthreads();
    for (int o = 128; o > 0; o >>= 1){
        if (t < o){ r1[t] = fmaxf(r1[t], r1[t + o]); r2[t] = fmaxf(r2[t], r2[t + o]); }
        __syncthreads();
    }
    float M1 = r1[0], M2 = r2[0];
    __syncthreads();
    float d1 = 0.f, num = 0.f, d2 = 0.f;
    for (int i = t; i < NPIX; i += 256){
        float s = row[i];
        int mk = mrow[i];
        float e1 = fast_exp(s - M1);
        d1 += e1;
        num += mk ? e1 : 0.f;
        d2 += fast_exp((mk ? -10000.f : s) - M2);
    }
    r1[t] = d1; r2[t] = num; r3[t] = d2;
    __syncthreads();
    for (int o = 128; o > 0; o >>= 1){
        if (t < o){ r1[t] += r1[t + o]; r2[t] += r2[t + o]; r3[t] += r3[t + o]; }
        __syncthreads();
    }
    if (t == 0){
        float* st = stats + ((size_t)b * NPIX + n) * 4;
        st[0] = M1; st[1] = r1[0]; st[2] = M2; st[3] = r3[0];
        conf[(size_t)b * NPIX + n] = r2[0] / r1[0];
    }
}

// -------- fused attention (tile n=64 x c=128, f32x2) --------
__global__ __launch_bounds__(256) void attn_out(
    const float* __restrict__ cor, const unsigned char* __restrict__ mask,
    const float* __restrict__ stats, const float* __restrict__ vh,
    const float* __restrict__ v2, float* __restrict__ out, float* __restrict__ out2)
{
    int b = blockIdx.z;
    int n0 = blockIdx.x * 64;
    int c0 = blockIdx.y * 128;
    __shared__ __align__(16) float2 P1d[16][66], P2d[16][66];
    __shared__ __align__(16) float  V1s[16][132], V2s[16][132];
    __shared__ float sM1[64], sD1[64], sM2[64], sD2[64];
    int tid = threadIdx.x, tx = tid & 15, ty = tid >> 4;
    if (tid < 64){
        const float* st = stats + ((size_t)b * NPIX + n0 + tid) * 4;
        sM1[tid] = st[0]; sD1[tid] = 1.f / st[1];
        sM2[tid] = st[2]; sD2[tid] = 1.f / st[3];
    }
    __syncthreads();
    unsigned long long acc1[4][4] = {}, acc2[4][4] = {};
    const float* vhb = vh + (size_t)b * CVCH * NPIX;
    const float* v2b = v2 + (size_t)b * CVCH * NPIX;
    const float* corb = cor + (size_t)b * NPIX * NPIX;
    const unsigned char* mb = mask + (size_t)b * NPIX * NPIX;
    for (int m0 = 0; m0 < NPIX; m0 += 16){
#pragma unroll
        for (int i = 0; i < 4; ++i){
            int idx = tid + 256 * i;
            int kk = idx & 15, r = idx >> 4;
            float s = corb[(size_t)(n0 + r) * NPIX + m0 + kk];
            int mk = mb[(size_t)(n0 + r) * NPIX + m0 + kk];
            float e1 = fast_exp(s - sM1[r]);
            float p1 = mk ? e1 * sD1[r] : 0.f;
            float p2 = fast_exp((mk ? -10000.f : s) - sM2[r]) * sD2[r];
            P1d[kk][r] = make_float2(p1, p1);
            P2d[kk][r] = make_float2(p2, p2);
        }
#pragma unroll
        for (int i = 0; i < 8; ++i){
            int idx = tid + 256 * i;
            int kk = idx & 15, r = idx >> 4;   // r: 0..127
            V1s[kk][r] = vhb[(size_t)(c0 + r) * NPIX + m0 + kk];
            V2s[kk][r] = v2b[(size_t)(c0 + r) * NPIX + m0 + kk];
        }
        __syncthreads();
#pragma unroll
        for (int kk = 0; kk < 16; ++kk){
            ulonglong2 p1a = *(const ulonglong2*)&P1d[kk][ty * 4];
            ulonglong2 p1b = *(const ulonglong2*)&P1d[kk][ty * 4 + 2];
            ulonglong2 p2a = *(const ulonglong2*)&P2d[kk][ty * 4];
            ulonglong2 p2b = *(const ulonglong2*)&P2d[kk][ty * 4 + 2];
            ulonglong2 w1a = *(const ulonglong2*)&V1s[kk][tx * 8];
            ulonglong2 w1b = *(const ulonglong2*)&V1s[kk][tx * 8 + 4];
            ulonglong2 w2a = *(const ulonglong2*)&V2s[kk][tx * 8];
            ulonglong2 w2b = *(const ulonglong2*)&V2s[kk][tx * 8 + 4];
            unsigned long long pa1[4] = {p1a.x, p1a.y, p1b.x, p1b.y};
            unsigned long long pa2[4] = {p2a.x, p2a.y, p2b.x, p2b.y};
            unsigned long long wa1[4] = {w1a.x, w1a.y, w1b.x, w1b.y};
            unsigned long long wa2[4] = {w2a.x, w2a.y, w2b.x, w2b.y};
#pragma unroll
            for (int i = 0; i < 4; ++i)
#pragma unroll
                for (int j = 0; j < 4; ++j){
                    acc1[i][j] = ffma2(pa1[i], wa1[j], acc1[i][j]);
                    acc2[i][j] = ffma2(pa2[i], wa2[j], acc2[i][j]);
                }
        }
        __syncthreads();
    }
    size_t obase = (size_t)b * CVCH * NPIX;
#pragma unroll
    for (int jp = 0; jp < 4; ++jp){
        int c = c0 + tx * 8 + jp * 2;
        float2 a0 = asf2(acc1[0][jp]), a1 = asf2(acc1[1][jp]), a2 = asf2(acc1[2][jp]), a3 = asf2(acc1[3][jp]);
        float2 b0 = asf2(acc2[0][jp]), b1 = asf2(acc2[1][jp]), b2 = asf2(acc2[2][jp]), b3 = asf2(acc2[3][jp]);
        *(float4*)&out [obase + (size_t)c * NPIX + n0 + ty * 4]       = make_float4(a0.x, a1.x, a2.x, a3.x);
        *(float4*)&out [obase + (size_t)(c + 1) * NPIX + n0 + ty * 4] = make_float4(a0.y, a1.y, a2.y, a3.y);
        *(float4*)&out2[obase + (size_t)c * NPIX + n0 + ty * 4]       = make_float4(b0.x, b1.x, b2.x, b3.x);
        *(float4*)&out2[obase + (size_t)(c + 1) * NPIX + n0 + ty * 4] = make_float4(b0.y, b1.y, b2.y, b3.y);
    }
}

// -------- instance-norm stats of q --------
__global__ void inorm_stats(const float* __restrict__ q, float* __restrict__ inst){
    int bc = blockIdx.x;
    const float* p = q + (size_t)bc * NPIX;
    int t = threadIdx.x;
    float s = 0.f, ss = 0.f;
    for (int i = t; i < NPIX; i += 256){ float v = p[i]; s += v; ss += v * v; }
    __shared__ float rs[256], rss[256];
    rs[t] = s; rss[t] = ss;
    __syncthreads();
    for (int o = 128; o > 0; o >>= 1){
        if (t < o){ rs[t] += rs[t + o]; rss[t] += rss[t + o]; }
        __syncthreads();
    }
    if (t == 0){
        float m = rs[0] / NPIX;
        float var = rss[0] / NPIX - m * m;
        inst[bc * 2] = m;
        inst[bc * 2 + 1] = rsqrtf(var + 1e-5f);
    }
}

// -------- fuse: ypre = out + (1-conf)*spade + q; pono stats --------
__global__ __launch_bounds__(256) void fuse1(
    const float* __restrict__ outb, const float* __restrict__ q,
    const float* __restrict__ gamma, const float* __restrict__ beta,
    const float* __restrict__ inst, const float* __restrict__ conf,
    float* __restrict__ ypre, float* __restrict__ pst)
{
    int b = blockIdx.x >> 6, y = blockIdx.x & 63;
    int tid = threadIdx.x;
    int x = tid & 63, cl = tid >> 6;
    int n = y * 64 + x;
    float one_m = 1.f - conf[(size_t)b * NPIX + n];
    size_t base = (size_t)b * CVCH * NPIX + n;
    float s = 0.f, ss = 0.f;
    for (int c = cl; c < CVCH; c += 4){
        size_t o = base + (size_t)c * NPIX;
        float qq = q[o];
        float im = inst[((size_t)b * CVCH + c) * 2];
        float is = inst[((size_t)b * CVCH + c) * 2 + 1];
        float sp = (qq - im) * is * (1.f + gamma[o]) + beta[o];
        float v = outb[o] + one_m * sp + qq;
        ypre[o] = v;
        s += v; ss += v * v;
    }
    __shared__ float rs[4][64], rss[4][64];
    rs[cl][x] = s; rss[cl][x] = ss;
    __syncthreads();
    if (cl == 0){
        float S  = rs[0][x] + rs[1][x] + rs[2][x] + rs[3][x];
        float SS = rss[0][x] + rss[1][x] + rss[2][x] + rss[3][x];
        float m = S / 256.f;
        float var = SS / 256.f - m * m;
        pst[((size_t)b * NPIX + n) * 2] = m;
        pst[((size_t)b * NPIX + n) * 2 + 1] = rsqrtf(var + 1e-5f);
    }
}

__global__ void fuse2(const float* __restrict__ ypre, const float* __restrict__ pst,
                      float* __restrict__ ypad){
    int idx = blockIdx.x * blockDim.x + threadIdx.x;
    if (idx >= BATCH * CVCH * NPIX) return;
    int n = idx & (NPIX - 1);
    int c = (idx >> 12) & 255;
    int b = idx >> 20;
    float m  = pst[((size_t)b * NPIX + n) * 2];
    float is = pst[((size_t)b * NPIX + n) * 2 + 1];
    int yy = n >> 6, xx = n & 63;
    ypad[(size_t)b * CVCH * PADN + (size_t)c * PADN + (size_t)(yy + 1) * PADW + xx + 1]
        = (ypre[idx] - m) * is;
}

extern "C" void kernel_launch(void* const* d_in, const int* in_sizes, int n_in,
                              void* d_out, int out_size){
    float* arena = nullptr;
    cudaGetSymbolAddress((void**)&arena, g_arena);

    const float* q    = (const float*)d_in[0];
    const float* k    = (const float*)d_in[1];
    const float* v    = (const float*)d_in[2];
    const float* pos  = (const float*)d_in[3];
    const float* v2   = (const float*)d_in[5];

    float* res  = (float*)d_out;
    float* out2 = res + (size_t)BATCH * CVCH * NPIX;
    float* cor  = out2 + (size_t)BATCH * CVCH * NPIX;

    float* QUERY = arena + OFF_QUERY;
    float* KEYT  = arena + OFF_KEYT;
    float* QF    = arena + OFF_QF;
    float* KF    = arena + OFF_KF;
    float* QP    = arena + OFF_QP;
    float* KP    = arena + OFF_KP;
    float* VH    = arena + OFF_VH;
    float* OUTB  = arena + OFF_OUT;
    float* STATS = arena + OFF_STATS;
    float* CONF  = arena + OFF_CONF;
    float* ACTV  = arena + OFF_ACTV;
    float* GAMMA = arena + OFF_GAMMA;
    float* BETA  = arena + OFF_BETA;
    float* INST  = arena + OFF_INST;
    float* YPRE  = arena + OFF_YPRE;
    float* PST   = arena + OFF_PST;
    float* YPAD  = arena + OFF_YPAD;
    float* T1PAD = arena + OFF_T1PAD;
    float* SEGP  = arena + OFF_SEGP;
    float* WT    = arena + OFF_WT;
    unsigned char* MASK = (unsigned char*)(arena + OFF_MASK);

    auto T = [&](int si, size_t off, int M, int K, int taps){
        int tot = M * K * taps;
        transpose_w<<<(tot + 255) / 256, 256>>>((const float*)d_in[si], WT + off, M, K, taps);
    };
    T(6,  WT_F,   320, 320, 1);
    T(8,  WT_G,   320, 320, 1);
    T(10, WT_H,   256, 256, 1);
    T(12, WT_FP,  64,  320, 1);
    T(14, WT_GP,  64,  320, 1);
    T(16, WT_SPS, 128, 3,   9);
    T(18, WT_SPG, 256, 128, 9);
    T(20, WT_SPB, 256, 128, 9);
    T(22, WT_R1,  256, 256, 9);
    T(24, WT_R2,  256, 256, 9);

    pad_seg<<<(BATCH * 3 * PADN + 255) / 256, 256>>>((const float*)d_in[4], SEGP);
    norm_concat<<<dim3(BATCH * 64, 2), 256>>>(q, k, pos, QUERY, KEYT);

    long sQK = (long)CQKCH * NPIX, sCV = (long)CVCH * NPIX, sDP = (long)DPCH * NPIX;
    gemm_wx<<<dim3(32, 5, 2), 256>>>(WT + WT_F,  QUERY, (const float*)d_in[7],  QF, 320, 320, 1, sQK, NPIX, sQK, 0, 0, nullptr, 0);
    gemm_wx<<<dim3(32, 5, 2), 256>>>(WT + WT_G,  KEYT,  (const float*)d_in[9],  KF, 320, 320, 1, sQK, NPIX, sQK, 0, 0, nullptr, 0);
    gemm_wx<<<dim3(32, 4, 2), 256>>>(WT + WT_H,  v,     (const float*)d_in[11], VH, 256, 256, 1, sCV, NPIX, sCV, 0, 0, nullptr, 0);
    gemm_wx<<<dim3(32, 1, 2), 256>>>(WT + WT_FP, QUERY, (const float*)d_in[13], QP, 64,  320, 1, sQK, NPIX, sDP, 0, 0, nullptr, 0);
    gemm_wx<<<dim3(32, 1, 2), 256>>>(WT + WT_GP, KEYT,  (const float*)d_in[15], KP, 64,  320, 1, sQK, NPIX, sDP, 0, 0, nullptr, 0);

    gemm_corr<<<dim3(32, 64, 2), 256>>>(QF, KF, QP, KP, cor, MASK);
    row_stats<<<dim3(NPIX, BATCH), 256>>>(cor, MASK, STATS, CONF);
    attn_out<<<dim3(64, 2, 2), 256>>>(cor, MASK, STATS, VH, v2, OUTB, out2);

    int nACTV = BATCH * NHID * PADN, nPAD = BATCH * CVCH * PADN;
    zero_kernel<<<(nACTV + 255) / 256, 256>>>(ACTV, nACTV);
    zero_kernel<<<(nPAD + 255) / 256, 256>>>(YPAD, nPAD);
    zero_kernel<<<(nPAD + 255) / 256, 256>>>(T1PAD, nPAD);

    gemm_wx<<<dim3(32, 2, 2), 256>>>(WT + WT_SPS, SEGP, (const float*)d_in[17], ACTV, 128, 3,   9, (long)3 * PADN,    PADN, (long)NHID * PADN, 1, 1, nullptr, 0);
    gemm_wx<<<dim3(32, 4, 2), 256>>>(WT + WT_SPG, ACTV, (const float*)d_in[19], GAMMA, 256, 128, 9, (long)NHID * PADN, PADN, sCV, 0, 0, nullptr, 0);
    gemm_wx<<<dim3(32, 4, 2), 256>>>(WT + WT_SPB, ACTV, (const float*)d_in[21], BETA,  256, 128, 9, (long)NHID * PADN, PADN, sCV, 0, 0, nullptr, 0);

    inorm_stats<<<BATCH * CVCH, 256>>>(q, INST);
    fuse1<<<BATCH * 64, 256>>>(OUTB, q, GAMMA, BETA, INST, CONF, YPRE, PST);
    fuse2<<<(BATCH * CVCH * NPIX + 255) / 256, 256>>>(YPRE, PST, YPAD);

    gemm_wx<<<dim3(32, 4, 2), 256>>>(WT + WT_R1, YPAD,  (const float*)d_in[23], T1PAD, 256, 256, 9, (long)CVCH * PADN, PADN, (long)CVCH * PADN, 1, 1, nullptr, 0);
    gemm_wx<<<dim3(32, 4, 2), 256>>>(WT + WT_R2, T1PAD, (const float*)d_in[25], res,   256, 256, 9, (long)CVCH * PADN, PADN, sCV, 0, 0, YPAD, (long)CVCH * PADN);
}

// round 9
// speedup vs baseline: 2.7148x; 2.7148x over previous
#include <cuda_runtime.h>
#include <math.h>
#include <stdint.h>

#define NPIX 4096
#define PADW 66
#define PADN 4356
#define BATCH 2
#define CVCH 256
#define CQKCH 320
#define DPCH 64
#define NHID 128

// ---------------- scratch arena ----------------
constexpr size_t SZ_QK = (size_t)BATCH * CQKCH * NPIX;
constexpr size_t SZ_CV = (size_t)BATCH * CVCH * NPIX;
constexpr size_t SZ_DP = (size_t)BATCH * DPCH * NPIX;

constexpr size_t OFF_QUERY = 0;
constexpr size_t OFF_KEYT  = OFF_QUERY + SZ_QK;
constexpr size_t OFF_QF    = OFF_KEYT + SZ_QK;
constexpr size_t OFF_KF    = OFF_QF + SZ_QK;
constexpr size_t OFF_QP    = OFF_KF + SZ_QK;
constexpr size_t OFF_KP    = OFF_QP + SZ_DP;
constexpr size_t OFF_VH    = OFF_KP + SZ_DP;
constexpr size_t OFF_OUT   = OFF_VH + SZ_CV;
constexpr size_t OFF_STATS = OFF_OUT + SZ_CV;
constexpr size_t OFF_CONF  = OFF_STATS + (size_t)BATCH*NPIX*4;
constexpr size_t OFF_ACTV  = OFF_CONF + (size_t)BATCH*NPIX;
constexpr size_t OFF_GAMMA = OFF_ACTV + (size_t)BATCH*NHID*PADN;
constexpr size_t OFF_BETA  = OFF_GAMMA + SZ_CV;
constexpr size_t OFF_INST  = OFF_BETA + SZ_CV;
constexpr size_t OFF_YPRE  = OFF_INST + (size_t)BATCH*CVCH*2;
constexpr size_t OFF_PST   = OFF_YPRE + SZ_CV;
constexpr size_t OFF_YPAD  = OFF_PST + (size_t)BATCH*NPIX*2;
constexpr size_t OFF_T1PAD = OFF_YPAD + (size_t)BATCH*CVCH*PADN;
constexpr size_t OFF_SEGP  = OFF_T1PAD + (size_t)BATCH*CVCH*PADN;
constexpr size_t OFF_VHT   = OFF_SEGP + 26176;
constexpr size_t OFF_V2T   = OFF_VHT + SZ_CV;
constexpr size_t OFF_WT    = OFF_V2T + SZ_CV;
constexpr size_t WT_F   = 0;
constexpr size_t WT_G   = WT_F  + 320*320;
constexpr size_t WT_H   = WT_G  + 320*320;
constexpr size_t WT_FP  = WT_H  + 256*256;
constexpr size_t WT_GP  = WT_FP + 320*64;
constexpr size_t WT_SPS = WT_GP + 320*64;
constexpr size_t WT_SPG = WT_SPS + 9*3*128;
constexpr size_t WT_SPB = WT_SPG + 9*128*256;
constexpr size_t WT_R1  = WT_SPB + 9*128*256;
constexpr size_t WT_R2  = WT_R1  + 9*256*256;
constexpr size_t WT_END = WT_R2  + 9*256*256;
constexpr size_t OFF_MASK = OFF_WT + ((WT_END + 63) & ~(size_t)63);
constexpr size_t ARENA_FLOATS = OFF_MASK + ((size_t)BATCH*NPIX*NPIX)/4 + 64;

__device__ __align__(16) float g_arena[ARENA_FLOATS];

// ---------------- helpers ----------------
__device__ __forceinline__ uint32_t f2tf32(float v){
    uint32_t r;
    asm("cvt.rna.tf32.f32 %0, %1;" : "=r"(r) : "f"(v));
    return r;
}

__device__ __forceinline__ void mma_tf32(float* d, const uint32_t* a, const uint32_t* b){
    asm volatile("mma.sync.aligned.m16n8k8.row.col.f32.tf32.tf32.f32 "
        "{%0,%1,%2,%3}, {%4,%5,%6,%7}, {%8,%9}, {%0,%1,%2,%3};"
        : "+f"(d[0]), "+f"(d[1]), "+f"(d[2]), "+f"(d[3])
        : "r"(a[0]), "r"(a[1]), "r"(a[2]), "r"(a[3]), "r"(b[0]), "r"(b[1]));
}

// exp(x) for x <= 0, FMA-pipe poly. rel err ~1e-6. (used in row_stats)
__device__ __forceinline__ float fast_exp(float x){
    float t = x * 1.4426950408889634f;
    t = fmaxf(t, -126.0f);
    float tr = t + 12582912.0f;
    int   k  = __float_as_int(tr) - 0x4B400000;
    float fi = tr - 12582912.0f;
    float f  = t - fi;
    float p = 1.0f + f*(0.6931471805599453f + f*(0.2402265069591007f
              + f*(0.0555041086648216f + f*0.0096181291076285f)));
    return p * __int_as_float((k + 127) << 23);
}

// ---------------- utility kernels ----------------
__global__ void zero_kernel(float* p, int n){
    int i = blockIdx.x * blockDim.x + threadIdx.x;
    if (i < n) p[i] = 0.f;
}

__global__ void transpose_w(const float* __restrict__ src, float* __restrict__ dst,
                            int M, int K, int taps){
    int idx = blockIdx.x * blockDim.x + threadIdx.x;
    if (idx >= M * K * taps) return;
    int t = idx / (K * M);
    int r = idx % (K * M);
    int k = r / M;
    int m = r % M;
    dst[idx] = src[((size_t)m * K + k) * taps + t];
}

// [b][c][m] -> [b][m][c]
__global__ __launch_bounds__(256) void transpose_cm(const float* __restrict__ src,
                                                    float* __restrict__ dst){
    __shared__ float s[32][33];
    int mBase = blockIdx.x * 32, cBase = blockIdx.y * 32, b = blockIdx.z;
    int tx = threadIdx.x & 31, ty = threadIdx.x >> 5;
    size_t base = (size_t)b * CVCH * NPIX;
#pragma unroll
    for (int i = 0; i < 4; ++i){
        int c = cBase + ty + i * 8;
        s[ty + i * 8][tx] = src[base + (size_t)c * NPIX + mBase + tx];
    }
    __syncthreads();
#pragma unroll
    for (int i = 0; i < 4; ++i){
        int m = mBase + ty + i * 8;
        dst[base + (size_t)m * CVCH + cBase + tx] = s[tx][ty + i * 8];
    }
}

__global__ void pad_seg(const float* __restrict__ seg, float* __restrict__ dst){
    int idx = blockIdx.x * blockDim.x + threadIdx.x;
    if (idx >= BATCH * 3 * PADN) return;
    int bc = idx / PADN;
    int r = idx % PADN;
    int yy = r / PADW, xx = r % PADW;
    float v = 0.f;
    if (yy >= 1 && yy <= 64 && xx >= 1 && xx <= 64)
        v = seg[(size_t)bc * NPIX + (yy - 1) * 64 + (xx - 1)];
    dst[idx] = v;
}

__global__ __launch_bounds__(256) void norm_concat(
    const float* __restrict__ q, const float* __restrict__ k,
    const float* __restrict__ pos, float* __restrict__ outq, float* __restrict__ outk){
    const float* src = blockIdx.y ? k : q;
    float* dst = blockIdx.y ? outk : outq;
    int b = blockIdx.x / 64, y = blockIdx.x % 64;
    int tid = threadIdx.x;
    int x = tid & 63, cl = tid >> 6;
    const float* sb = src + (size_t)b * CVCH * NPIX + y * 64;
    __shared__ float partial[4][64];
    __shared__ float inv[64];
    float ss = 0.f;
    for (int c = cl; c < CVCH; c += 4){ float v = sb[(size_t)c * NPIX + x]; ss += v * v; }
    partial[cl][x] = ss;
    __syncthreads();
    if (cl == 0){
        float s = partial[0][x] + partial[1][x] + partial[2][x] + partial[3][x];
        inv[x] = 1.f / (sqrtf(s) + 2.220446049250313e-16f);
    }
    __syncthreads();
    float* db = dst + (size_t)b * CQKCH * NPIX + y * 64;
    float iv = inv[x];
    for (int c = cl; c < CVCH; c += 4) db[(size_t)c * NPIX + x] = sb[(size_t)c * NPIX + x] * iv;
    const float* pb = pos + y * 64;
    for (int i = tid; i < 64 * 64; i += 256){
        int cp = i >> 6, xx = i & 63;
        db[(size_t)(CVCH + cp) * NPIX + xx] = pb[(size_t)cp * NPIX + xx];
    }
}

// ------------- exact-fp32 1x1 conv GEMM (for QP/KP — mask sign sensitivity) -------------
__global__ __launch_bounds__(256) void gemm_wx_f32(
    const float* __restrict__ Wt, const float* __restrict__ X,
    const float* __restrict__ bias, float* __restrict__ Cout,
    int M, int K, long xBatchStride, int xChanStride, long cBatchStride)
{
    int b = blockIdx.z;
    int n0 = blockIdx.x * 64;
    int m0 = blockIdx.y * 64;
    const float* Xb = X + (size_t)b * xBatchStride;
    __shared__ __align__(16) float As[16][64];
    __shared__ __align__(16) float Bs[16][64];
    float acc[4][4] = {};
    int tid = threadIdx.x;
    int tx = tid & 15, ty = tid >> 4;
    for (int k0 = 0; k0 < K; k0 += 16){
#pragma unroll
        for (int i = 0; i < 4; ++i){
            int idx = tid + 256 * i;
            int kk = idx >> 6, col = idx & 63;
            int kg = k0 + kk;
            As[kk][col] = (kg < K) ? Wt[(size_t)kg * M + m0 + col] : 0.f;
            Bs[kk][col] = (kg < K) ? Xb[(size_t)kg * xChanStride + n0 + col] : 0.f;
        }
        __syncthreads();
#pragma unroll
        for (int kk = 0; kk < 16; ++kk){
            float4 a  = *(const float4*)&As[kk][ty * 4];
            float4 bb = *(const float4*)&Bs[kk][tx * 4];
            float av[4] = {a.x, a.y, a.z, a.w};
            float bv[4] = {bb.x, bb.y, bb.z, bb.w};
#pragma unroll
            for (int i = 0; i < 4; ++i)
#pragma unroll
                for (int j = 0; j < 4; ++j)
                    acc[i][j] += av[i] * bv[j];
        }
        __syncthreads();
    }
#pragma unroll
    for (int i = 0; i < 4; ++i){
        int m = m0 + ty * 4 + i;
        float bvv = bias ? bias[m] : 0.f;
#pragma unroll
        for (int j = 0; j < 4; ++j)
            Cout[(size_t)b * cBatchStride + (size_t)m * NPIX + n0 + tx * 4 + j] = acc[i][j] + bvv;
    }
}

// ------------- unified tf32 tensor-core GEMM -------------
__global__ __launch_bounds__(256) void gemm_tf32(
    const float* __restrict__ A, long aBatchStride, int aRowStride,
    const float* __restrict__ X, long xBatchStride, int xChanStride,
    const float* __restrict__ bias, float* __restrict__ Cout, long cBatchStride,
    int K, int taps, int relu, int outPadded, float scale,
    const float* __restrict__ addsrc, long addBatchStride)
{
    int b = blockIdx.z;
    int n0 = blockIdx.x * 128;
    int m0 = blockIdx.y * 64;
    const float* A_ = A + (size_t)b * aBatchStride;
    const float* Xb = X + (size_t)b * xBatchStride;
    __shared__ float As[16][72];
    __shared__ float Bs[16][136];
    int tid = threadIdx.x;
    int wid = tid >> 5, lane = tid & 31;
    int gid = lane >> 2, tig = lane & 3;
    int warpM = wid & 1, warpN = wid >> 1;
    float acc[2][4][4];
#pragma unroll
    for (int mi = 0; mi < 2; ++mi)
#pragma unroll
        for (int ni = 0; ni < 4; ++ni)
#pragma unroll
            for (int p = 0; p < 4; ++p) acc[mi][ni][p] = 0.f;

    int Ktot = K * taps;
    for (int k0 = 0; k0 < Ktot; k0 += 16){
#pragma unroll
        for (int i = 0; i < 4; ++i){
            int idx = tid + i * 256;
            int kk = idx >> 6, m = idx & 63;
            int kg = k0 + kk;
            float v = (kg < Ktot) ? A_[(size_t)kg * aRowStride + m0 + m] : 0.f;
            As[kk][m] = __uint_as_float(f2tf32(v));
        }
        int tapU = -1, kyU = 0, kxU = 0, krBase = 0;
        if (taps > 1 && (K & 15) == 0){
            tapU = k0 / K; kyU = tapU / 3; kxU = tapU % 3; krBase = k0 - tapU * K;
        }
#pragma unroll
        for (int i = 0; i < 8; ++i){
            int idx = tid + i * 256;
            int kk = idx >> 7, col = idx & 127;
            int kg = k0 + kk;
            float v = 0.f;
            if (kg < Ktot){
                if (taps == 1){
                    v = Xb[(size_t)kg * xChanStride + n0 + col];
                } else {
                    int tap, kr, ky, kx;
                    if (tapU >= 0){ tap = tapU; kr = krBase + kk; ky = kyU; kx = kxU; }
                    else { tap = kg / K; kr = kg - tap * K; ky = tap / 3; kx = tap % 3; }
                    int n = n0 + col, yy = n >> 6, xx = n & 63;
                    v = Xb[(size_t)kr * xChanStride + (yy + ky) * PADW + xx + kx];
                }
            }
            Bs[kk][col] = __uint_as_float(f2tf32(v));
        }
        __syncthreads();
#pragma unroll
        for (int ks = 0; ks < 16; ks += 8){
            uint32_t afr[2][4], bfr[4][2];
#pragma unroll
            for (int mi = 0; mi < 2; ++mi){
                int mb = warpM * 32 + mi * 16 + gid;
                afr[mi][0] = __float_as_uint(As[ks + tig][mb]);
                afr[mi][1] = __float_as_uint(As[ks + tig][mb + 8]);
                afr[mi][2] = __float_as_uint(As[ks + tig + 4][mb]);
                afr[mi][3] = __float_as_uint(As[ks + tig + 4][mb + 8]);
            }
#pragma unroll
            for (int ni = 0; ni < 4; ++ni){
                int nb = warpN * 32 + ni * 8 + gid;
                bfr[ni][0] = __float_as_uint(Bs[ks + tig][nb]);
                bfr[ni][1] = __float_as_uint(Bs[ks + tig + 4][nb]);
            }
#pragma unroll
            for (int mi = 0; mi < 2; ++mi)
#pragma unroll
                for (int ni = 0; ni < 4; ++ni)
                    mma_tf32(acc[mi][ni], afr[mi], bfr[ni]);
        }
        __syncthreads();
    }

    size_t cb = (size_t)b * cBatchStride;
#pragma unroll
    for (int mi = 0; mi < 2; ++mi)
#pragma unroll
        for (int ni = 0; ni < 4; ++ni)
#pragma unroll
            for (int p = 0; p < 4; ++p){
                int row = m0 + warpM * 32 + mi * 16 + gid + (p >> 1) * 8;
                int n   = n0 + warpN * 32 + ni * 8 + 2 * tig + (p & 1);
                float vv = acc[mi][ni][p] * scale + (bias ? bias[row] : 0.f);
                if (relu) vv = fmaxf(vv, 0.f);
                int yy = n >> 6, xx = n & 63;
                if (addsrc)
                    vv += addsrc[(size_t)b * addBatchStride + (size_t)row * PADN + (size_t)(yy + 1) * PADW + xx + 1];
                if (outPadded)
                    Cout[cb + (size_t)row * PADN + (size_t)(yy + 1) * PADW + xx + 1] = vv;
                else
                    Cout[cb + (size_t)row * NPIX + n] = vv;
            }
}

// ---------------- mask GEMM in exact fp32 (sign-sensitive) ----------------
__global__ __launch_bounds__(256) void mask_gemm(
    const float* __restrict__ qp, const float* __restrict__ kp,
    unsigned char* __restrict__ mask)
{
    int b = blockIdx.z;
    int n0 = blockIdx.y * 64, m0 = blockIdx.x * 64;
    __shared__ __align__(16) float As[16][64];
    __shared__ __align__(16) float Bs[16][64];
    int tid = threadIdx.x, tx = tid & 15, ty = tid >> 4;
    float acc[4][4] = {};
    const float* Ap = qp + (size_t)b * DPCH * NPIX + n0;
    const float* Bp = kp + (size_t)b * DPCH * NPIX + m0;
    for (int k0 = 0; k0 < DPCH; k0 += 16){
#pragma unroll
        for (int i = 0; i < 4; ++i){
            int idx = tid + 256 * i;
            int kk = idx >> 6, col = idx & 63;
            As[kk][col] = Ap[(size_t)(k0 + kk) * NPIX + col];
            Bs[kk][col] = Bp[(size_t)(k0 + kk) * NPIX + col];
        }
        __syncthreads();
#pragma unroll
        for (int kk = 0; kk < 16; ++kk){
            float4 a  = *(const float4*)&As[kk][ty * 4];
            float4 bb = *(const float4*)&Bs[kk][tx * 4];
            float av[4] = {a.x, a.y, a.z, a.w};
            float bv[4] = {bb.x, bb.y, bb.z, bb.w};
#pragma unroll
            for (int i = 0; i < 4; ++i)
#pragma unroll
                for (int j = 0; j < 4; ++j)
                    acc[i][j] += av[i] * bv[j];
        }
        __syncthreads();
    }
    size_t base = (size_t)b * NPIX * NPIX;
#pragma unroll
    for (int i = 0; i < 4; ++i){
        int n = n0 + ty * 4 + i;
#pragma unroll
        for (int j = 0; j < 4; ++j)
            mask[base + (size_t)n * NPIX + m0 + tx * 4 + j] = (acc[i][j] > 0.f) ? 1 : 0;
    }
}

// -------- per-row softmax stats (both variants) + conf --------
__global__ __launch_bounds__(256) void row_stats(
    const float* __restrict__ cor, const unsigned char* __restrict__ mask,
    float* __restrict__ stats, float* __restrict__ conf)
{
    int b = blockIdx.y, n = blockIdx.x;
    const float* row = cor + ((size_t)b * NPIX + n) * NPIX;
    const unsigned char* mrow = mask + ((size_t)b * NPIX + n) * NPIX;
    int t = threadIdx.x;
    float m1 = -1e30f, m2 = -1e30f;
    for (int i = t; i < NPIX; i += 256){
        float s = row[i];
        m1 = fmaxf(m1, s);
        m2 = fmaxf(m2, mrow[i] ? -10000.f : s);
    }
    __shared__ float r1[256], r2[256], r3[256];
    r1[t] = m1; r2[t] = m2;
    __syncthreads();
    for (int o = 128; o > 0; o >>= 1){
        if (t < o){ r1[t] = fmaxf(r1[t], r1[t + o]); r2[t] = fmaxf(r2[t], r2[t + o]); }
        __syncthreads();
    }
    float M1 = r1[0], M2 = r2[0];
    __syncthreads();
    float d1 = 0.f, num = 0.f, d2 = 0.f;
    for (int i = t; i < NPIX; i += 256){
        float s = row[i];
        int mk = mrow[i];
        float e1 = fast_exp(s - M1);
        d1 += e1;
        num += mk ? e1 : 0.f;
        d2 += fast_exp((mk ? -10000.f : s) - M2);
    }
    r1[t] = d1; r2[t] = num; r3[t] = d2;
    __syncthreads();
    for (int o = 128; o > 0; o >>= 1){
        if (t < o){ r1[t] += r1[t + o]; r2[t] += r2[t + o]; r3[t] += r3[t + o]; }
        __syncthreads();
    }
    if (t == 0){
        float* st = stats + ((size_t)b * NPIX + n) * 4;
        st[0] = M1; st[1] = r1[0]; st[2] = M2; st[3] = r3[0];
        conf[(size_t)b * NPIX + n] = r2[0] / r1[0];
    }
}

// -------- tensor-core attention: out[n,c] = sum_m P[n,m] * VT[m,c] --------
__global__ __launch_bounds__(256) void attn_tf32(
    const float* __restrict__ cor, const unsigned char* __restrict__ mask,
    const float* __restrict__ stats, const float* __restrict__ VT1,
    const float* __restrict__ VT2, float* __restrict__ out1, float* __restrict__ out2)
{
    int b = blockIdx.z;
    int var = blockIdx.y;
    int n0 = blockIdx.x * 64;
    const float* VT = var ? VT2 : VT1;
    float* outp = var ? out2 : out1;
    __shared__ float Ps[16][72];
    __shared__ float Vs[16][264];
    int tid = threadIdx.x;
    int wid = tid >> 5, lane = tid & 31;
    int gid = lane >> 2, tig = lane & 3;
    int warpM = wid & 1, warpN = wid >> 1;

    int pr = tid >> 2, pq = tid & 3;
    const float* st = stats + ((size_t)b * NPIX + n0 + pr) * 4;
    float Mv = var ? st[2] : st[0];
    float Dv = 1.f / (var ? st[3] : st[1]);

    const float* corb = cor + (size_t)b * NPIX * NPIX;
    const unsigned char* mb = mask + (size_t)b * NPIX * NPIX;
    const float* VTb = VT + (size_t)b * NPIX * CVCH;

    float acc[2][8][4];
#pragma unroll
    for (int mi = 0; mi < 2; ++mi)
#pragma unroll
        for (int ni = 0; ni < 8; ++ni)
#pragma unroll
            for (int p = 0; p < 4; ++p) acc[mi][ni][p] = 0.f;

    for (int m0 = 0; m0 < NPIX; m0 += 16){
        {
            size_t off = (size_t)(n0 + pr) * NPIX + m0 + pq * 4;
            float4 s4 = *(const float4*)&corb[off];
            unsigned int mk4 = *(const unsigned int*)&mb[off];
            float sv[4] = {s4.x, s4.y, s4.z, s4.w};
#pragma unroll
            for (int j = 0; j < 4; ++j){
                int mk = (mk4 >> (8 * j)) & 0xff;
                float p;
                if (var == 0) p = mk ? __expf(sv[j] - Mv) * Dv : 0.f;
                else          p = __expf((mk ? -10000.f : sv[j]) - Mv) * Dv;
                Ps[pq * 4 + j][pr] = __uint_as_float(f2tf32(p));
            }
        }
#pragma unroll
        for (int i = 0; i < 4; ++i){
            int slot = tid + i * 256;
            int kk = slot >> 6, c4 = slot & 63;
            float4 v4 = *(const float4*)&VTb[(size_t)(m0 + kk) * CVCH + c4 * 4];
            Vs[kk][c4 * 4 + 0] = __uint_as_float(f2tf32(v4.x));
            Vs[kk][c4 * 4 + 1] = __uint_as_float(f2tf32(v4.y));
            Vs[kk][c4 * 4 + 2] = __uint_as_float(f2tf32(v4.z));
            Vs[kk][c4 * 4 + 3] = __uint_as_float(f2tf32(v4.w));
        }
        __syncthreads();
#pragma unroll
        for (int ks = 0; ks < 16; ks += 8){
            uint32_t afr[2][4], bfr[8][2];
#pragma unroll
            for (int mi = 0; mi < 2; ++mi){
                int mbx = warpM * 32 + mi * 16 + gid;
                afr[mi][0] = __float_as_uint(Ps[ks + tig][mbx]);
                afr[mi][1] = __float_as_uint(Ps[ks + tig][mbx + 8]);
                afr[mi][2] = __float_as_uint(Ps[ks + tig + 4][mbx]);
                afr[mi][3] = __float_as_uint(Ps[ks + tig + 4][mbx + 8]);
            }
#pragma unroll
            for (int ni = 0; ni < 8; ++ni){
                int nb = warpN * 64 + ni * 8 + gid;
                bfr[ni][0] = __float_as_uint(Vs[ks + tig][nb]);
                bfr[ni][1] = __float_as_uint(Vs[ks + tig + 4][nb]);
            }
#pragma unroll
            for (int mi = 0; mi < 2; ++mi)
#pragma unroll
                for (int ni = 0; ni < 8; ++ni)
                    mma_tf32(acc[mi][ni], afr[mi], bfr[ni]);
        }
        __syncthreads();
    }

    size_t obase = (size_t)b * CVCH * NPIX;
#pragma unroll
    for (int mi = 0; mi < 2; ++mi)
#pragma unroll
        for (int ni = 0; ni < 8; ++ni)
#pragma unroll
            for (int p = 0; p < 4; ++p){
                int n = n0 + warpM * 32 + mi * 16 + gid + (p >> 1) * 8;
                int c = warpN * 64 + ni * 8 + 2 * tig + (p & 1);
                outp[obase + (size_t)c * NPIX + n] = acc[mi][ni][p];
            }
}

// -------- instance-norm stats of q --------
__global__ void inorm_stats(const float* __restrict__ q, float* __restrict__ inst){
    int bc = blockIdx.x;
    const float* p = q + (size_t)bc * NPIX;
    int t = threadIdx.x;
    float s = 0.f, ss = 0.f;
    for (int i = t; i < NPIX; i += 256){ float v = p[i]; s += v; ss += v * v; }
    __shared__ float rs[256], rss[256];
    rs[t] = s; rss[t] = ss;
    __syncthreads();
    for (int o = 128; o > 0; o >>= 1){
        if (t < o){ rs[t] += rs[t + o]; rss[t] += rss[t + o]; }
        __syncthreads();
    }
    if (t == 0){
        float m = rs[0] / NPIX;
        float var = rss[0] / NPIX - m * m;
        inst[bc * 2] = m;
        inst[bc * 2 + 1] = rsqrtf(var + 1e-5f);
    }
}

// -------- fuse: ypre = out + (1-conf)*spade + q; pono stats --------
__global__ __launch_bounds__(256) void fuse1(
    const float* __restrict__ outb, const float* __restrict__ q,
    const float* __restrict__ gamma, const float* __restrict__ beta,
    const float* __restrict__ inst, const float* __restrict__ conf,
    float* __restrict__ ypre, float* __restrict__ pst)
{
    int b = blockIdx.x >> 6, y = blockIdx.x & 63;
    int tid = threadIdx.x;
    int x = tid & 63, cl = tid >> 6;
    int n = y * 64 + x;
    float one_m = 1.f - conf[(size_t)b * NPIX + n];
    size_t base = (size_t)b * CVCH * NPIX + n;
    float s = 0.f, ss = 0.f;
    for (int c = cl; c < CVCH; c += 4){
        size_t o = base + (size_t)c * NPIX;
        float qq = q[o];
        float im = inst[((size_t)b * CVCH + c) * 2];
        float is = inst[((size_t)b * CVCH + c) * 2 + 1];
        float sp = (qq - im) * is * (1.f + gamma[o]) + beta[o];
        float v = outb[o] + one_m * sp + qq;
        ypre[o] = v;
        s += v; ss += v * v;
    }
    __shared__ float rs[4][64], rss[4][64];
    rs[cl][x] = s; rss[cl][x] = ss;
    __syncthreads();
    if (cl == 0){
        float S  = rs[0][x] + rs[1][x] + rs[2][x] + rs[3][x];
        float SS = rss[0][x] + rss[1][x] + rss[2][x] + rss[3][x];
        float m = S / 256.f;
        float var = SS / 256.f - m * m;
        pst[((size_t)b * NPIX + n) * 2] = m;
        pst[((size_t)b * NPIX + n) * 2 + 1] = rsqrtf(var + 1e-5f);
    }
}

__global__ void fuse2(const float* __restrict__ ypre, const float* __restrict__ pst,
                      float* __restrict__ ypad){
    int idx = blockIdx.x * blockDim.x + threadIdx.x;
    if (idx >= BATCH * CVCH * NPIX) return;
    int n = idx & (NPIX - 1);
    int c = (idx >> 12) & 255;
    int b = idx >> 20;
    float m  = pst[((size_t)b * NPIX + n) * 2];
    float is = pst[((size_t)b * NPIX + n) * 2 + 1];
    int yy = n >> 6, xx = n & 63;
    ypad[(size_t)b * CVCH * PADN + (size_t)c * PADN + (size_t)(yy + 1) * PADW + xx + 1]
        = (ypre[idx] - m) * is;
}

extern "C" void kernel_launch(void* const* d_in, const int* in_sizes, int n_in,
                              void* d_out, int out_size){
    float* arena = nullptr;
    cudaGetSymbolAddress((void**)&arena, g_arena);

    const float* q    = (const float*)d_in[0];
    const float* k    = (const float*)d_in[1];
    const float* v    = (const float*)d_in[2];
    const float* pos  = (const float*)d_in[3];
    const float* v2   = (const float*)d_in[5];

    float* res  = (float*)d_out;
    float* out2 = res + (size_t)BATCH * CVCH * NPIX;
    float* cor  = out2 + (size_t)BATCH * CVCH * NPIX;

    float* QUERY = arena + OFF_QUERY;
    float* KEYT  = arena + OFF_KEYT;
    float* QF    = arena + OFF_QF;
    float* KF    = arena + OFF_KF;
    float* QP    = arena + OFF_QP;
    float* KP    = arena + OFF_KP;
    float* VH    = arena + OFF_VH;
    float* OUTB  = arena + OFF_OUT;
    float* STATS = arena + OFF_STATS;
    float* CONF  = arena + OFF_CONF;
    float* ACTV  = arena + OFF_ACTV;
    float* GAMMA = arena + OFF_GAMMA;
    float* BETA  = arena + OFF_BETA;
    float* INST  = arena + OFF_INST;
    float* YPRE  = arena + OFF_YPRE;
    float* PST   = arena + OFF_PST;
    float* YPAD  = arena + OFF_YPAD;
    float* T1PAD = arena + OFF_T1PAD;
    float* SEGP  = arena + OFF_SEGP;
    float* VHT   = arena + OFF_VHT;
    float* V2T   = arena + OFF_V2T;
    float* WT    = arena + OFF_WT;
    unsigned char* MASK = (unsigned char*)(arena + OFF_MASK);

    auto T = [&](int si, size_t off, int M, int K, int taps){
        int tot = M * K * taps;
        transpose_w<<<(tot + 255) / 256, 256>>>((const float*)d_in[si], WT + off, M, K, taps);
    };
    T(6,  WT_F,   320, 320, 1);
    T(8,  WT_G,   320, 320, 1);
    T(10, WT_H,   256, 256, 1);
    T(12, WT_FP,  64,  320, 1);
    T(14, WT_GP,  64,  320, 1);
    T(16, WT_SPS, 128, 3,   9);
    T(18, WT_SPG, 256, 128, 9);
    T(20, WT_SPB, 256, 128, 9);
    T(22, WT_R1,  256, 256, 9);
    T(24, WT_R2,  256, 256, 9);

    pad_seg<<<(BATCH * 3 * PADN + 255) / 256, 256>>>((const float*)d_in[4], SEGP);
    norm_concat<<<dim3(BATCH * 64, 2), 256>>>(q, k, pos, QUERY, KEYT);

    long sQK = (long)CQKCH * NPIX, sCV = (long)CVCH * NPIX, sDP = (long)DPCH * NPIX;
    long sCOR = (long)NPIX * NPIX;

    // 1x1 convs — tf32 for value paths, EXACT fp32 for mask logits (QP/KP)
    gemm_tf32<<<dim3(32, 5, 2), 256>>>(WT + WT_F,  0, 320, QUERY, sQK, NPIX,
        (const float*)d_in[7],  QF, sQK, 320, 1, 0, 0, 1.f, nullptr, 0);
    gemm_tf32<<<dim3(32, 5, 2), 256>>>(WT + WT_G,  0, 320, KEYT,  sQK, NPIX,
        (const float*)d_in[9],  KF, sQK, 320, 1, 0, 0, 1.f, nullptr, 0);
    gemm_tf32<<<dim3(32, 4, 2), 256>>>(WT + WT_H,  0, 256, v,     sCV, NPIX,
        (const float*)d_in[11], VH, sCV, 256, 1, 0, 0, 1.f, nullptr, 0);
    gemm_wx_f32<<<dim3(64, 1, 2), 256>>>(WT + WT_FP, QUERY, (const float*)d_in[13],
        QP, 64, 320, sQK, NPIX, sDP);
    gemm_wx_f32<<<dim3(64, 1, 2), 256>>>(WT + WT_GP, KEYT,  (const float*)d_in[15],
        KP, 64, 320, sQK, NPIX, sDP);

    // cor = (QF^T KF) / sqrt(320)  (tf32)
    gemm_tf32<<<dim3(32, 64, 2), 256>>>(QF, sQK, NPIX, KF, sQK, NPIX,
        nullptr, cor, sCOR, 320, 1, 0, 0, 0.0559016994f, nullptr, 0);
    // mask in exact fp32 (sign-sensitive)
    mask_gemm<<<dim3(64, 64, 2), 256>>>(QP, KP, MASK);

    row_stats<<<dim3(NPIX, BATCH), 256>>>(cor, MASK, STATS, CONF);

    // transpose V operands to [m][c]
    transpose_cm<<<dim3(128, 8, 2), 256>>>(VH, VHT);
    transpose_cm<<<dim3(128, 8, 2), 256>>>(v2, V2T);

    attn_tf32<<<dim3(64, 2, 2), 256>>>(cor, MASK, STATS, VHT, V2T, OUTB, out2);

    // SPADE path
    int nACTV = BATCH * NHID * PADN, nPAD = BATCH * CVCH * PADN;
    zero_kernel<<<(nACTV + 255) / 256, 256>>>(ACTV, nACTV);
    zero_kernel<<<(nPAD + 255) / 256, 256>>>(YPAD, nPAD);
    zero_kernel<<<(nPAD + 255) / 256, 256>>>(T1PAD, nPAD);

    gemm_tf32<<<dim3(32, 2, 2), 256>>>(WT + WT_SPS, 0, 128, SEGP, (long)3 * PADN, PADN,
        (const float*)d_in[17], ACTV, (long)NHID * PADN, 3, 9, 1, 1, 1.f, nullptr, 0);
    gemm_tf32<<<dim3(32, 4, 2), 256>>>(WT + WT_SPG, 0, 256, ACTV, (long)NHID * PADN, PADN,
        (const float*)d_in[19], GAMMA, sCV, 128, 9, 0, 0, 1.f, nullptr, 0);
    gemm_tf32<<<dim3(32, 4, 2), 256>>>(WT + WT_SPB, 0, 256, ACTV, (long)NHID * PADN, PADN,
        (const float*)d_in[21], BETA, sCV, 128, 9, 0, 0, 1.f, nullptr, 0);

    inorm_stats<<<BATCH * CVCH, 256>>>(q, INST);
    fuse1<<<BATCH * 64, 256>>>(OUTB, q, GAMMA, BETA, INST, CONF, YPRE, PST);
    fuse2<<<(BATCH * CVCH * NPIX + 255) / 256, 256>>>(YPRE, PST, YPAD);

    gemm_tf32<<<dim3(32, 4, 2), 256>>>(WT + WT_R1, 0, 256, YPAD, (long)CVCH * PADN, PADN,
        (const float*)d_in[23], T1PAD, (long)CVCH * PADN, 256, 9, 1, 1, 1.f, nullptr, 0);
    gemm_tf32<<<dim3(32, 4, 2), 256>>>(WT + WT_R2, 0, 256, T1PAD, (long)CVCH * PADN, PADN,
        (const float*)d_in[25], res, sCV, 256, 9, 0, 0, 1.f, YPAD, (long)CVCH * PADN);
}